// round 9
// baseline (speedup 1.0000x reference)
#include <cuda_runtime.h>
#include <cstdint>

namespace {
constexpr int kB  = 1024;
constexpr int kL  = 26;
constexpr int kA  = 8192;
constexpr int kC1 = 256;
constexpr int kD  = 512;
constexpr int kE  = 1024;
constexpr int kM  = kB * kL;      // 26624
constexpr float kThr = 1e-6f;
constexpr int LDSW  = 36;         // gemm4 smem row stride (floats): BK=32 + 4 pad
constexpr int HT_LD = 20;         // GRU h-tile stride
constexpr int WS_LD = 516;        // GRU resident w_hh stride
}

// ---------------- scratch (allocation-free) ----------------
__device__ float g_h1[(size_t)kM * kC1];
__device__ float g_h2[(size_t)kM * kD];
__device__ float g_gi[(size_t)kM * 3 * kD];
__device__ float g_hA[(size_t)kB * kD];
__device__ float g_hB[(size_t)kB * kD];
__device__ float g_rw1[(size_t)kC1 * kA];
__device__ float g_rw2[(size_t)kD * kC1];
__device__ float g_rwih[(size_t)3 * kD * kD];
__device__ float g_rlin[(size_t)kE * kD];
__device__ unsigned g_bar_count = 0;
__device__ unsigned g_bar_gen   = 0;

// ---------------- helpers ----------------
__device__ __forceinline__ uint32_t f2tf32(float f) {
    uint32_t u;
    asm("cvt.rna.tf32.f32 %0, %1;" : "=r"(u) : "f"(f));
    return u;
}
__device__ __forceinline__ void mma_tf32(float d[4], const uint32_t a[4], const uint32_t b[2]) {
    asm volatile(
        "mma.sync.aligned.m16n8k8.row.col.f32.tf32.tf32.f32 "
        "{%0,%1,%2,%3}, {%4,%5,%6,%7}, {%8,%9}, {%0,%1,%2,%3};"
        : "+f"(d[0]), "+f"(d[1]), "+f"(d[2]), "+f"(d[3])
        : "r"(a[0]), "r"(a[1]), "r"(a[2]), "r"(a[3]), "r"(b[0]), "r"(b[1]));
}
__device__ __forceinline__ void cp16(uint32_t saddr, const float* g) {
    asm volatile("cp.async.cg.shared.global [%0], [%1], 16;\n" :: "r"(saddr), "l"(g));
}
__device__ __forceinline__ uint32_t smem_u32(const void* p) {
    uint32_t a;
    asm("{ .reg .u64 t; cvta.to.shared.u64 t, %1; cvt.u32.u64 %0, t; }" : "=r"(a) : "l"(p));
    return a;
}
__device__ __forceinline__ void ldsm4(uint32_t r[4], uint32_t saddr) {
    asm volatile("ldmatrix.sync.aligned.m8n8.x4.shared.b16 {%0,%1,%2,%3}, [%4];"
        : "=r"(r[0]), "=r"(r[1]), "=r"(r[2]), "=r"(r[3]) : "r"(saddr));
}
__device__ __forceinline__ float sigm(float x)  { return 1.f / (1.f + __expf(-x)); }
__device__ __forceinline__ float tanhq(float x) { return 1.f - 2.f / (1.f + __expf(2.f * x)); }

// ---------------- pre-round weights to tf32 ----------------
__global__ void round_tf32(const float* __restrict__ in, float* __restrict__ out, int n4) {
    int i = blockIdx.x * blockDim.x + threadIdx.x;
    if (i < n4) {
        float4 v = ((const float4*)in)[i];
        v.x = __uint_as_float(f2tf32(v.x));
        v.y = __uint_as_float(f2tf32(v.y));
        v.z = __uint_as_float(f2tf32(v.z));
        v.w = __uint_as_float(f2tf32(v.w));
        ((float4*)out)[i] = v;
    }
}

// ---------------- GEMM v4b ----------------
// C[M,N] = A[M,K] * B[N,K]^T + bias.  128x128 CTA tile, 512 threads (4x4 warp
// grid, 32x32 warp tiles), BK=32, 4-stage cp.async ring with 3-deep in-flight
// (issue(kt+3) targets stage (kt+3)&3 != kt&3), register-double-buffered
// ldmatrix fragments.
template<bool THRESH, bool CVT_A, bool ROUND_OUT>
__global__ void __launch_bounds__(512, 1)
gemm4(const float* __restrict__ Ag, const float* __restrict__ Bg,
      const float* __restrict__ bias, float* __restrict__ Cg,
      int M, int N, int K, int ntiles, int tn)
{
    extern __shared__ float sm[];
    constexpr int AS = 128 * LDSW;    // floats per A stage
    constexpr int SS = 2 * AS;        // floats per (A+B) stage
    const int tid  = threadIdx.x;
    const int lane = tid & 31, warp = tid >> 5;
    const int wr = warp & 3, wc = warp >> 2;     // 4x4 warp grid
    const int grp = lane >> 2, tig = lane & 3;
    const int sel = lane >> 3, rw = lane & 7;
    const int NT = K >> 5;
    const uint32_t smb = smem_u32(sm);

    // cp.async mapping: 2 16B chunks of A + 2 of B per thread per stage
    int lr[2], lk[2];
#pragma unroll
    for (int i = 0; i < 2; i++) { int l = tid + i * 512; lr[i] = l >> 3; lk[i] = (l & 7) << 2; }

    // ldmatrix base addresses (stage 0, k = 0)
    uint32_t adA[2], adB[2];
#pragma unroll
    for (int mi = 0; mi < 2; mi++) {
        const int row = wr * 32 + mi * 16 + ((sel & 1) << 3) + rw;
        adA[mi] = smb + (uint32_t)(row * LDSW + ((sel >> 1) << 2)) * 4u;
    }
#pragma unroll
    for (int p = 0; p < 2; p++) {
        const int row = wc * 32 + p * 16 + ((sel >> 1) << 3) + rw;
        adB[p] = smb + (uint32_t)(AS + row * LDSW + ((sel & 1) << 2)) * 4u;
    }

    for (int tile = blockIdx.x; tile < ntiles; tile += gridDim.x) {
        const int bm = (tile / tn) << 7;
        const int bn = (tile % tn) << 7;
        const float* Ab = Ag + (size_t)bm * K;
        const float* Bb = Bg + (size_t)bn * K;

        auto issue = [&](int kt) {
            const uint32_t st = (uint32_t)(kt & 3);
            const int go = kt << 5;
#pragma unroll
            for (int i = 0; i < 2; i++) {
                uint32_t sa = smb + (st * SS + (uint32_t)(lr[i] * LDSW + lk[i])) * 4u;
                cp16(sa,           Ab + (size_t)lr[i] * K + go + lk[i]);
                cp16(sa + AS * 4u, Bb + (size_t)lr[i] * K + go + lk[i]);
            }
            asm volatile("cp.async.commit_group;\n");
        };

        float acc[2][4][4];
#pragma unroll
        for (int a = 0; a < 2; a++)
#pragma unroll
            for (int b = 0; b < 4; b++)
#pragma unroll
                for (int c = 0; c < 4; c++) acc[a][b][c] = 0.f;

        issue(0); issue(1); issue(2);

        uint32_t af[2][2][4], bq[2][2][4];   // [buf][frag][reg]

        for (int kt = 0; kt < NT; kt++) {
            const int rem = NT - 1 - kt;
            if (rem >= 2)      asm volatile("cp.async.wait_group 2;\n");
            else if (rem == 1) asm volatile("cp.async.wait_group 1;\n");
            else               asm volatile("cp.async.wait_group 0;\n");
            __syncthreads();
            if (kt + 3 < NT) issue(kt + 3);

            const uint32_t stoff = (uint32_t)((kt & 3) * SS) * 4u;
            // prefetch k8 step 0
            ldsm4(af[0][0], adA[0] + stoff);
            ldsm4(af[0][1], adA[1] + stoff);
            ldsm4(bq[0][0], adB[0] + stoff);
            ldsm4(bq[0][1], adB[1] + stoff);
#pragma unroll
            for (int ks = 0; ks < 4; ks++) {
                const int cur = ks & 1, nxt = cur ^ 1;
                if (ks < 3) {
                    const uint32_t ko = stoff + (uint32_t)((ks + 1) * 8) * 4u;
                    ldsm4(af[nxt][0], adA[0] + ko);
                    ldsm4(af[nxt][1], adA[1] + ko);
                    ldsm4(bq[nxt][0], adB[0] + ko);
                    ldsm4(bq[nxt][1], adB[1] + ko);
                }
                if (CVT_A) {
#pragma unroll
                    for (int mi = 0; mi < 2; mi++)
#pragma unroll
                        for (int j = 0; j < 4; j++)
                            af[cur][mi][j] = f2tf32(__uint_as_float(af[cur][mi][j]));
                }
#pragma unroll
                for (int mi = 0; mi < 2; mi++)
#pragma unroll
                    for (int p = 0; p < 2; p++) {
                        mma_tf32(acc[mi][2 * p],     af[cur][mi], &bq[cur][p][0]);
                        mma_tf32(acc[mi][2 * p + 1], af[cur][mi], &bq[cur][p][2]);
                    }
            }
        }
        __syncthreads();   // protect stages before next tile's prologue

        // epilogue
#pragma unroll
        for (int mi = 0; mi < 2; mi++) {
            const int r0 = bm + wr * 32 + mi * 16 + grp;
#pragma unroll
            for (int ni = 0; ni < 4; ni++) {
                const int c0 = bn + wc * 32 + ni * 8 + tig * 2;
                const float b0 = bias[c0], b1 = bias[c0 + 1];
                float v00 = acc[mi][ni][0] + b0, v01 = acc[mi][ni][1] + b1;
                float v10 = acc[mi][ni][2] + b0, v11 = acc[mi][ni][3] + b1;
                if (THRESH) {
                    v00 = (v00 > kThr) ? v00 : 0.f;  v01 = (v01 > kThr) ? v01 : 0.f;
                    v10 = (v10 > kThr) ? v10 : 0.f;  v11 = (v11 > kThr) ? v11 : 0.f;
                }
                if (ROUND_OUT) {
                    v00 = __uint_as_float(f2tf32(v00)); v01 = __uint_as_float(f2tf32(v01));
                    v10 = __uint_as_float(f2tf32(v10)); v11 = __uint_as_float(f2tf32(v11));
                }
                *(float2*)&Cg[(size_t)r0 * N + c0]       = make_float2(v00, v01);
                *(float2*)&Cg[(size_t)(r0 + 8) * N + c0] = make_float2(v10, v11);
            }
        }
    }
}

// ---------------- grid barrier (grid=128 <= 148 SMs, 1 CTA/SM) ----------------
__device__ __forceinline__ void grid_barrier() {
    __syncthreads();
    if (threadIdx.x == 0) {
        unsigned gen = *((volatile unsigned*)&g_bar_gen);
        __threadfence();
        if (atomicAdd(&g_bar_count, 1u) == gridDim.x - 1) {
            atomicExch(&g_bar_count, 0u);
            __threadfence();
            atomicAdd(&g_bar_gen, 1u);
        } else {
            while (*((volatile unsigned*)&g_bar_gen) == gen) { __nanosleep(32); }
            __threadfence();
        }
    }
    __syncthreads();
}

// ---------------- persistent fused GRU (3-stage, 2-deep: correct) -------------
__global__ void __launch_bounds__(256, 1)
gru_persistent(const float* __restrict__ gi, const float* __restrict__ w_hh,
               const float* __restrict__ b_hh,
               float* __restrict__ hA, float* __restrict__ hB)
{
    extern __shared__ float smf[];
    float* ws = smf;                      // [96][WS_LD] resident w_hh slice
    float* ht = smf + 96 * WS_LD;         // 3 stages x [128][HT_LD]
    constexpr int HTS = 128 * HT_LD;

    const int tid  = threadIdx.x;
    const int lane = tid & 31, warp = tid >> 5;
    const int grp = lane >> 2, tig = lane & 3;
    const int sel = lane >> 3, rw = lane & 7;
    const int mt = blockIdx.x >> 4;
    const int jc = blockIdx.x & 15;
    const int m0 = mt * 128, j0 = jc * 32;

    for (int i4 = tid; i4 < 96 * 128; i4 += 256) {
        const int row = i4 >> 7, k4 = (i4 & 127) << 2;
        const int g = row >> 5, c = row & 31;
        float4 v = *(const float4*)(w_hh + (size_t)(g * kD + j0 + c) * kD + k4);
        v.x = __uint_as_float(f2tf32(v.x));
        v.y = __uint_as_float(f2tf32(v.y));
        v.z = __uint_as_float(f2tf32(v.z));
        v.w = __uint_as_float(f2tf32(v.w));
        *(float4*)(ws + row * WS_LD + k4) = v;
    }

    float bhh0[12], bhh1[12];
#pragma unroll
    for (int ni = 0; ni < 12; ni++) {
        const int g = ni >> 2, j = j0 + (ni & 3) * 8 + tig * 2;
        bhh0[ni] = b_hh[g * kD + j];
        bhh1[ni] = b_hh[g * kD + j + 1];
    }
    __syncthreads();

    int lr[2], lk[2];
#pragma unroll
    for (int i = 0; i < 2; i++) { int l = tid + i * 256; lr[i] = l >> 2; lk[i] = (l & 3) << 2; }
    const uint32_t smb_ht = smem_u32(ht);
    const uint32_t smb_ws = smem_u32(ws);

    uint32_t adA, adB[6];
    {
        const int row = warp * 16 + ((sel & 1) << 3) + rw;
        adA = smb_ht + (uint32_t)(row * HT_LD + ((sel >> 1) << 2)) * 4u;
    }
#pragma unroll
    for (int p = 0; p < 6; p++) {
        const int row = p * 16 + ((sel >> 1) << 3) + rw;
        adB[p] = smb_ws + (uint32_t)(row * WS_LD + ((sel & 1) << 2)) * 4u;
    }

    for (int t = 0; t < kL; t++) {
        float* src = (t & 1) ? hA : hB;
        float* dst = (t & 1) ? hB : hA;

        float acc[12][4];
#pragma unroll
        for (int a = 0; a < 12; a++)
#pragma unroll
            for (int c = 0; c < 4; c++) acc[a][c] = 0.f;

        if (t > 0) {
            const float* Ab = src + (size_t)m0 * kD;
            auto issue = [&](int kt) {
                const int st = kt % 3;
                const int go = kt << 4;
#pragma unroll
                for (int i = 0; i < 2; i++) {
                    uint32_t sa = smb_ht + (uint32_t)(st * HTS + lr[i] * HT_LD + lk[i]) * 4u;
                    cp16(sa, Ab + (size_t)lr[i] * kD + go + lk[i]);
                }
                asm volatile("cp.async.commit_group;\n");
            };
            issue(0); issue(1);

            uint32_t af[2][4], bq[2][6][4];
            for (int kt = 0; kt < 32; kt++) {
                if (kt + 1 < 32) asm volatile("cp.async.wait_group 1;\n");
                else             asm volatile("cp.async.wait_group 0;\n");
                __syncthreads();
                if (kt + 2 < 32) issue(kt + 2);

                const uint32_t stoff = (uint32_t)((kt % 3) * HTS) * 4u;
                const uint32_t kk0 = (uint32_t)(kt << 4) * 4u;
                // prefetch ks=0
                ldsm4(af[0], adA + stoff);
#pragma unroll
                for (int p = 0; p < 6; p++) ldsm4(bq[0][p], adB[p] + kk0);
#pragma unroll
                for (int ks = 0; ks < 2; ks++) {
                    const int cur = ks;
                    if (ks == 0) {
                        ldsm4(af[1], adA + stoff + 32u);
#pragma unroll
                        for (int p = 0; p < 6; p++) ldsm4(bq[1][p], adB[p] + kk0 + 32u);
                    }
#pragma unroll
                    for (int p = 0; p < 6; p++) {
                        mma_tf32(acc[2 * p],     af[cur], &bq[cur][p][0]);
                        mma_tf32(acc[2 * p + 1], af[cur], &bq[cur][p][2]);
                    }
                }
            }
            __syncthreads();
        }

        // fused gate update: acc[q]=gh_r, acc[q+4]=gh_z, acc[q+8]=gh_n
#pragma unroll
        for (int q = 0; q < 4; q++) {
#pragma unroll
            for (int s = 0; s < 2; s++) {
                const int b  = m0 + warp * 16 + grp + s * 8;
                const int jj = j0 + q * 8 + tig * 2;
                const float* gib = gi + ((size_t)b * kL + t) * (3 * kD);
                const float2 gr = *(const float2*)(gib + jj);
                const float2 gz = *(const float2*)(gib + kD + jj);
                const float2 gn = *(const float2*)(gib + 2 * kD + jj);
                float2 hp = make_float2(0.f, 0.f);
                if (t > 0) hp = *(const float2*)(src + (size_t)b * kD + jj);
                const float r0 = sigm(gr.x + acc[q][2 * s]     + bhh0[q]);
                const float r1 = sigm(gr.y + acc[q][2 * s + 1] + bhh1[q]);
                const float z0 = sigm(gz.x + acc[q + 4][2 * s]     + bhh0[q + 4]);
                const float z1 = sigm(gz.y + acc[q + 4][2 * s + 1] + bhh1[q + 4]);
                const float n0 = tanhq(gn.x + r0 * (acc[q + 8][2 * s]     + bhh0[q + 8]));
                const float n1 = tanhq(gn.y + r1 * (acc[q + 8][2 * s + 1] + bhh1[q + 8]));
                float h0 = (1.f - z0) * n0 + z0 * hp.x;
                float h1 = (1.f - z1) * n1 + z1 * hp.y;
                h0 = __uint_as_float(f2tf32(h0));
                h1 = __uint_as_float(f2tf32(h1));
                *(float2*)(dst + (size_t)b * kD + jj) = make_float2(h0, h1);
            }
        }
        if (t < kL - 1) grid_barrier();
    }
}

// ---------------- host ----------------
extern "C" void kernel_launch(void* const* d_in, const int* in_sizes, int n_in,
                              void* d_out, int out_size)
{
    (void)in_sizes; (void)n_in; (void)out_size;
    const float* x     = (const float*)d_in[0];
    const float* w1    = (const float*)d_in[1];
    const float* b1    = (const float*)d_in[2];
    const float* w2    = (const float*)d_in[3];
    const float* b2    = (const float*)d_in[4];
    const float* w_ih  = (const float*)d_in[5];
    const float* w_hh  = (const float*)d_in[6];
    const float* b_ih  = (const float*)d_in[7];
    const float* b_hh  = (const float*)d_in[8];
    const float* lin_w = (const float*)d_in[9];
    const float* lin_b = (const float*)d_in[10];
    float* out = (float*)d_out;

    float *h1, *h2, *gi, *hA, *hB, *rw1, *rw2, *rwih, *rlin;
    cudaGetSymbolAddress((void**)&h1,   g_h1);
    cudaGetSymbolAddress((void**)&h2,   g_h2);
    cudaGetSymbolAddress((void**)&gi,   g_gi);
    cudaGetSymbolAddress((void**)&hA,   g_hA);
    cudaGetSymbolAddress((void**)&hB,   g_hB);
    cudaGetSymbolAddress((void**)&rw1,  g_rw1);
    cudaGetSymbolAddress((void**)&rw2,  g_rw2);
    cudaGetSymbolAddress((void**)&rwih, g_rwih);
    cudaGetSymbolAddress((void**)&rlin, g_rlin);

    constexpr int GEMM_SMEM = 4 * 2 * 128 * LDSW * 4;              // 147456
    constexpr int GRU_SMEM  = (96 * WS_LD + 3 * 128 * HT_LD) * 4;  // 228864
    cudaFuncSetAttribute(gemm4<true,  true,  true >, cudaFuncAttributeMaxDynamicSharedMemorySize, GEMM_SMEM);
    cudaFuncSetAttribute(gemm4<true,  false, true >, cudaFuncAttributeMaxDynamicSharedMemorySize, GEMM_SMEM);
    cudaFuncSetAttribute(gemm4<false, false, false>, cudaFuncAttributeMaxDynamicSharedMemorySize, GEMM_SMEM);
    cudaFuncSetAttribute(gru_persistent,             cudaFuncAttributeMaxDynamicSharedMemorySize, GRU_SMEM);

    // pre-round weights to tf32
    round_tf32<<<(kC1 * kA / 4 + 255) / 256, 256>>>(w1,    rw1,  kC1 * kA / 4);
    round_tf32<<<(kD * kC1 / 4 + 255) / 256, 256>>>(w2,    rw2,  kD * kC1 / 4);
    round_tf32<<<(3 * kD * kD / 4 + 255) / 256, 256>>>(w_ih, rwih, 3 * kD * kD / 4);
    round_tf32<<<(kE * kD / 4 + 255) / 256, 256>>>(lin_w, rlin, kE * kD / 4);

    const int tm = kM / 128;   // 208

    // conv1: [26624,8192] x [256,8192]^T  (cvt A in-kernel; threshold+round out)
    gemm4<true, true, true ><<<tm * 2, 512, GEMM_SMEM>>>(
        x, rw1, b1, h1, kM, kC1, kA, tm * 2, 2);
    // conv2: [26624,256] x [512,256]^T
    gemm4<true, false, true ><<<tm * 4, 512, GEMM_SMEM>>>(
        h1, rw2, b2, h2, kM, kD, kC1, tm * 4, 4);
    // gi (all timesteps): [26624,512] x [1536,512]^T
    gemm4<false, false, false><<<tm * 12, 512, GEMM_SMEM>>>(
        h2, rwih, b_ih, gi, kM, 3 * kD, kD, tm * 12, 12);

    // fused persistent GRU: 26 steps, 1 launch (kL even -> final h lands in hB)
    gru_persistent<<<128, 256, GRU_SMEM>>>(gi, w_hh, b_hh, hA, hB);

    // out = h_last @ lin_w^T + lin_b : [1024,512] x [1024,512]^T
    gemm4<false, false, false><<<8 * 8, 512, GEMM_SMEM>>>(
        hB, rlin, lin_b, out, kB, kE, kD, 8 * 8, 8);
}

// round 10
// speedup vs baseline: 1.3591x; 1.3591x over previous
#include <cuda_runtime.h>
#include <cuda_fp16.h>
#include <cstdint>

namespace {
constexpr int kB  = 1024;
constexpr int kL  = 26;
constexpr int kA  = 8192;
constexpr int kC1 = 256;
constexpr int kD  = 512;
constexpr int kE  = 1024;
constexpr int kM  = kB * kL;      // 26624
constexpr float kThr = 1e-6f;
constexpr int LDF   = 20;         // tf32 gemm smem row stride (floats): BK=16 + 4
constexpr int LDH   = 40;         // fp16 gemm smem row stride (halves): BK=32 + 8 (80B: conflict-free)
constexpr int WS_LDH = 520;       // GRU resident w_hh stride (halves): 1040B ≡ 4 words mod 32 -> conflict-free
constexpr int HT_LDH = 40;        // GRU h-tile stride (halves)
}

// ---------------- scratch (allocation-free) ----------------
__device__ __half g_h1[(size_t)kM * kC1];
__device__ __half g_h2[(size_t)kM * kD];
__device__ float  g_gi[(size_t)kM * 3 * kD];
__device__ __half g_hA[(size_t)kB * kD];
__device__ __half g_hB[(size_t)kB * kD];
__device__ float  g_rw1[(size_t)kC1 * kA];      // tf32-rounded w1
__device__ __half g_rw2h[(size_t)kD * kC1];
__device__ __half g_rwihh[(size_t)3 * kD * kD];
__device__ __half g_rlinh[(size_t)kE * kD];
__device__ unsigned g_bar_count = 0;
__device__ unsigned g_bar_gen   = 0;

// ---------------- helpers ----------------
__device__ __forceinline__ uint32_t f2tf32(float f) {
    uint32_t u;
    asm("cvt.rna.tf32.f32 %0, %1;" : "=r"(u) : "f"(f));
    return u;
}
__device__ __forceinline__ void mma_tf32(float d[4], const uint32_t a[4], const uint32_t b[2]) {
    asm volatile(
        "mma.sync.aligned.m16n8k8.row.col.f32.tf32.tf32.f32 "
        "{%0,%1,%2,%3}, {%4,%5,%6,%7}, {%8,%9}, {%0,%1,%2,%3};"
        : "+f"(d[0]), "+f"(d[1]), "+f"(d[2]), "+f"(d[3])
        : "r"(a[0]), "r"(a[1]), "r"(a[2]), "r"(a[3]), "r"(b[0]), "r"(b[1]));
}
__device__ __forceinline__ void mma_f16(float d[4], const uint32_t a[4], uint32_t b0, uint32_t b1) {
    asm volatile(
        "mma.sync.aligned.m16n8k16.row.col.f32.f16.f16.f32 "
        "{%0,%1,%2,%3}, {%4,%5,%6,%7}, {%8,%9}, {%0,%1,%2,%3};"
        : "+f"(d[0]), "+f"(d[1]), "+f"(d[2]), "+f"(d[3])
        : "r"(a[0]), "r"(a[1]), "r"(a[2]), "r"(a[3]), "r"(b0), "r"(b1));
}
__device__ __forceinline__ void cp16(uint32_t saddr, const void* g) {
    asm volatile("cp.async.cg.shared.global [%0], [%1], 16;\n" :: "r"(saddr), "l"(g));
}
__device__ __forceinline__ uint32_t smem_u32(const void* p) {
    uint32_t a;
    asm("{ .reg .u64 t; cvta.to.shared.u64 t, %1; cvt.u32.u64 %0, t; }" : "=r"(a) : "l"(p));
    return a;
}
__device__ __forceinline__ void ldsm4(uint32_t r[4], uint32_t saddr) {
    asm volatile("ldmatrix.sync.aligned.m8n8.x4.shared.b16 {%0,%1,%2,%3}, [%4];"
        : "=r"(r[0]), "=r"(r[1]), "=r"(r[2]), "=r"(r[3]) : "r"(saddr));
}
__device__ __forceinline__ float sigm(float x)  { return 1.f / (1.f + __expf(-x)); }
__device__ __forceinline__ float tanhq(float x) { return 1.f - 2.f / (1.f + __expf(2.f * x)); }

// ---------------- weight pre-conversion ----------------
__global__ void round_tf32(const float* __restrict__ in, float* __restrict__ out, int n4) {
    int i = blockIdx.x * blockDim.x + threadIdx.x;
    if (i < n4) {
        float4 v = ((const float4*)in)[i];
        v.x = __uint_as_float(f2tf32(v.x));
        v.y = __uint_as_float(f2tf32(v.y));
        v.z = __uint_as_float(f2tf32(v.z));
        v.w = __uint_as_float(f2tf32(v.w));
        ((float4*)out)[i] = v;
    }
}
__global__ void round_f16(const float* __restrict__ in, __half* __restrict__ out, int n4) {
    int i = blockIdx.x * blockDim.x + threadIdx.x;
    if (i < n4) {
        float4 v = ((const float4*)in)[i];
        *(__half2*)(out + (size_t)i * 4)     = __floats2half2_rn(v.x, v.y);
        *(__half2*)(out + (size_t)i * 4 + 2) = __floats2half2_rn(v.z, v.w);
    }
}

// ---------------- GEMM tf32 (conv1 only; R5-proven skeleton, fp16 output) ----
// C[M,N](fp16) = thresh(A[M,K] * B[N,K]^T + bias).  128x128 CTA, 256 thr,
// 4x2 warps (32x64 tiles), BK=16, 4-stage cp.async, 1 sync/k-tile.
__global__ void __launch_bounds__(256, 2)
gemm_t32(const float* __restrict__ Ag, const float* __restrict__ Bg,
         const float* __restrict__ bias, __half* __restrict__ Cg,
         int M, int N, int K, int ntiles, int tn)
{
    extern __shared__ float smf[];
    constexpr int AS = 128 * LDF;
    constexpr int SS = 2 * AS;
    const int tid  = threadIdx.x;
    const int lane = tid & 31, warp = tid >> 5;
    const int wr = warp >> 1, wc = warp & 1;
    const int grp = lane >> 2, tig = lane & 3;
    const int sel = lane >> 3, rw = lane & 7;
    const int NT = K >> 4;
    const uint32_t smb = smem_u32(smf);

    int lr[2], lk[2];
#pragma unroll
    for (int i = 0; i < 2; i++) { int l = tid + i * 256; lr[i] = l >> 2; lk[i] = (l & 3) << 2; }

    uint32_t adA[2], adB[4];
#pragma unroll
    for (int mi = 0; mi < 2; mi++) {
        const int row = wr * 32 + mi * 16 + ((sel & 1) << 3) + rw;
        adA[mi] = smb + (uint32_t)(row * LDF + ((sel >> 1) << 2)) * 4u;
    }
#pragma unroll
    for (int p = 0; p < 4; p++) {
        const int row = wc * 64 + p * 16 + ((sel >> 1) << 3) + rw;
        adB[p] = smb + (uint32_t)(AS + row * LDF + ((sel & 1) << 2)) * 4u;
    }

    for (int tile = blockIdx.x; tile < ntiles; tile += gridDim.x) {
        const int bm = (tile / tn) << 7;
        const int bn = (tile % tn) << 7;
        const float* Ab = Ag + (size_t)bm * K;
        const float* Bb = Bg + (size_t)bn * K;

        auto issue = [&](int kt) {
            const int st = kt & 3;
            const int go = kt << 4;
#pragma unroll
            for (int i = 0; i < 2; i++) {
                uint32_t sa = smb + (uint32_t)(st * SS + lr[i] * LDF + lk[i]) * 4u;
                cp16(sa,           Ab + (size_t)lr[i] * K + go + lk[i]);
                cp16(sa + AS * 4u, Bb + (size_t)lr[i] * K + go + lk[i]);
            }
            asm volatile("cp.async.commit_group;\n");
        };

        float acc[2][8][4];
#pragma unroll
        for (int a = 0; a < 2; a++)
#pragma unroll
            for (int b = 0; b < 8; b++)
#pragma unroll
                for (int c = 0; c < 4; c++) acc[a][b][c] = 0.f;

        issue(0); issue(1); issue(2);

        for (int kt = 0; kt < NT; kt++) {
            const int rem = NT - 1 - kt;
            if (rem >= 2)      asm volatile("cp.async.wait_group 2;\n");
            else if (rem == 1) asm volatile("cp.async.wait_group 1;\n");
            else               asm volatile("cp.async.wait_group 0;\n");
            __syncthreads();
            if (kt + 3 < NT) issue(kt + 3);

            const uint32_t stoff = (uint32_t)((kt & 3) * SS) * 4u;
#pragma unroll
            for (int ks = 0; ks < 2; ks++) {
                const uint32_t koff = stoff + (uint32_t)(ks * 8) * 4u;
                uint32_t af[2][4], bq[4][4];
#pragma unroll
                for (int mi = 0; mi < 2; mi++) {
                    ldsm4(af[mi], adA[mi] + koff);
#pragma unroll
                    for (int j = 0; j < 4; j++)
                        af[mi][j] = f2tf32(__uint_as_float(af[mi][j]));  // x -> tf32 RN
                }
#pragma unroll
                for (int p = 0; p < 4; p++) ldsm4(bq[p], adB[p] + koff);
#pragma unroll
                for (int mi = 0; mi < 2; mi++)
#pragma unroll
                    for (int p = 0; p < 4; p++) {
                        mma_tf32(acc[mi][2 * p],     af[mi], &bq[p][0]);
                        mma_tf32(acc[mi][2 * p + 1], af[mi], &bq[p][2]);
                    }
            }
        }
        __syncthreads();

#pragma unroll
        for (int mi = 0; mi < 2; mi++) {
            const int r0 = bm + wr * 32 + mi * 16 + grp;
#pragma unroll
            for (int ni = 0; ni < 8; ni++) {
                const int c0 = bn + wc * 64 + ni * 8 + tig * 2;
                const float b0 = bias[c0], b1 = bias[c0 + 1];
                float v00 = acc[mi][ni][0] + b0, v01 = acc[mi][ni][1] + b1;
                float v10 = acc[mi][ni][2] + b0, v11 = acc[mi][ni][3] + b1;
                v00 = (v00 > kThr) ? v00 : 0.f;  v01 = (v01 > kThr) ? v01 : 0.f;
                v10 = (v10 > kThr) ? v10 : 0.f;  v11 = (v11 > kThr) ? v11 : 0.f;
                *(__half2*)&Cg[(size_t)r0 * N + c0]       = __floats2half2_rn(v00, v01);
                *(__half2*)&Cg[(size_t)(r0 + 8) * N + c0] = __floats2half2_rn(v10, v11);
            }
        }
    }
}

// ---------------- GEMM fp16 (conv2 / gi / lin) ----------------
// C[M,N] = A[M,K](f16) * B[N,K]^T(f16) + bias, f32 accum.  Same skeleton:
// 128x128 CTA, 256 thr, 4x2 warps, BK=32 halves, 4-stage ring, native
// ldmatrix b16, mma.m16n8k16.
template<bool THRESH, bool OUT16>
__global__ void __launch_bounds__(256, 2)
gemm_h(const __half* __restrict__ Ag, const __half* __restrict__ Bg,
       const float* __restrict__ bias, void* __restrict__ Cgv,
       int M, int N, int K, int ntiles, int tn)
{
    extern __shared__ __half smh[];
    constexpr int AS = 128 * LDH;     // halves per A stage
    constexpr int SS = 2 * AS;
    const int tid  = threadIdx.x;
    const int lane = tid & 31, warp = tid >> 5;
    const int wr = warp >> 1, wc = warp & 1;
    const int grp = lane >> 2, tig = lane & 3;
    const int sel = lane >> 3, rw = lane & 7;
    const int NT = K >> 5;
    const uint32_t smb = smem_u32(smh);

    int lr[2], lk[2];   // 16B chunk = 8 halves; 128 rows x 4 chunks per operand
#pragma unroll
    for (int i = 0; i < 2; i++) { int l = tid + i * 256; lr[i] = l >> 2; lk[i] = (l & 3) << 3; }

    uint32_t adA[2], adB[4];
#pragma unroll
    for (int mi = 0; mi < 2; mi++) {
        const int row = wr * 32 + mi * 16 + ((sel & 1) << 3) + rw;
        adA[mi] = smb + (uint32_t)(row * LDH + ((sel >> 1) << 3)) * 2u;
    }
#pragma unroll
    for (int p = 0; p < 4; p++) {
        const int row = wc * 64 + p * 16 + ((sel & 1) << 3) + rw;
        adB[p] = smb + (uint32_t)(AS + row * LDH + ((sel >> 1) << 3)) * 2u;
    }

    for (int tile = blockIdx.x; tile < ntiles; tile += gridDim.x) {
        const int bm = (tile / tn) << 7;
        const int bn = (tile % tn) << 7;
        const __half* Ab = Ag + (size_t)bm * K;
        const __half* Bb = Bg + (size_t)bn * K;

        auto issue = [&](int kt) {
            const int st = kt & 3;
            const int go = kt << 5;
#pragma unroll
            for (int i = 0; i < 2; i++) {
                uint32_t sa = smb + (uint32_t)(st * SS + lr[i] * LDH + lk[i]) * 2u;
                cp16(sa,           Ab + (size_t)lr[i] * K + go + lk[i]);
                cp16(sa + AS * 2u, Bb + (size_t)lr[i] * K + go + lk[i]);
            }
            asm volatile("cp.async.commit_group;\n");
        };

        float acc[2][8][4];
#pragma unroll
        for (int a = 0; a < 2; a++)
#pragma unroll
            for (int b = 0; b < 8; b++)
#pragma unroll
                for (int c = 0; c < 4; c++) acc[a][b][c] = 0.f;

        issue(0); issue(1); issue(2);

        for (int kt = 0; kt < NT; kt++) {
            const int rem = NT - 1 - kt;
            if (rem >= 2)      asm volatile("cp.async.wait_group 2;\n");
            else if (rem == 1) asm volatile("cp.async.wait_group 1;\n");
            else               asm volatile("cp.async.wait_group 0;\n");
            __syncthreads();
            if (kt + 3 < NT) issue(kt + 3);

            const uint32_t stoff = (uint32_t)((kt & 3) * SS) * 2u;
#pragma unroll
            for (int ks = 0; ks < 2; ks++) {            // two k16 steps
                const uint32_t koff = stoff + (uint32_t)(ks * 16) * 2u;
                uint32_t af[2][4], bq[4][4];
#pragma unroll
                for (int mi = 0; mi < 2; mi++) ldsm4(af[mi], adA[mi] + koff);
#pragma unroll
                for (int p = 0; p < 4; p++) ldsm4(bq[p], adB[p] + koff);
#pragma unroll
                for (int mi = 0; mi < 2; mi++)
#pragma unroll
                    for (int p = 0; p < 4; p++) {
                        // n-block p*16+0..7: {r0,r2}; p*16+8..15: {r1,r3}
                        mma_f16(acc[mi][2 * p],     af[mi], bq[p][0], bq[p][2]);
                        mma_f16(acc[mi][2 * p + 1], af[mi], bq[p][1], bq[p][3]);
                    }
            }
        }
        __syncthreads();

#pragma unroll
        for (int mi = 0; mi < 2; mi++) {
            const int r0 = bm + wr * 32 + mi * 16 + grp;
#pragma unroll
            for (int ni = 0; ni < 8; ni++) {
                const int c0 = bn + wc * 64 + ni * 8 + tig * 2;
                const float b0 = bias[c0], b1 = bias[c0 + 1];
                float v00 = acc[mi][ni][0] + b0, v01 = acc[mi][ni][1] + b1;
                float v10 = acc[mi][ni][2] + b0, v11 = acc[mi][ni][3] + b1;
                if (THRESH) {
                    v00 = (v00 > kThr) ? v00 : 0.f;  v01 = (v01 > kThr) ? v01 : 0.f;
                    v10 = (v10 > kThr) ? v10 : 0.f;  v11 = (v11 > kThr) ? v11 : 0.f;
                }
                if (OUT16) {
                    __half* Cg = (__half*)Cgv;
                    *(__half2*)&Cg[(size_t)r0 * N + c0]       = __floats2half2_rn(v00, v01);
                    *(__half2*)&Cg[(size_t)(r0 + 8) * N + c0] = __floats2half2_rn(v10, v11);
                } else {
                    float* Cg = (float*)Cgv;
                    *(float2*)&Cg[(size_t)r0 * N + c0]       = make_float2(v00, v01);
                    *(float2*)&Cg[(size_t)(r0 + 8) * N + c0] = make_float2(v10, v11);
                }
            }
        }
    }
}

// ---------------- grid barrier (grid=128 <= 148 SMs, 1 CTA/SM) ----------------
__device__ __forceinline__ void grid_barrier() {
    __syncthreads();
    if (threadIdx.x == 0) {
        unsigned gen = *((volatile unsigned*)&g_bar_gen);
        __threadfence();
        if (atomicAdd(&g_bar_count, 1u) == gridDim.x - 1) {
            atomicExch(&g_bar_count, 0u);
            __threadfence();
            atomicAdd(&g_bar_gen, 1u);
        } else {
            while (*((volatile unsigned*)&g_bar_gen) == gen) { __nanosleep(32); }
            __threadfence();
        }
    }
    __syncthreads();
}

// ---------------- persistent fused GRU (fp16 operands, f32 gates) -------------
// grid=128: CTA owns batch rows [mt*128,+128) x gate cols [jc*32,+32); resident
// fp16 w_hh slice (96 x 512) in smem all 26 steps; h ping-pong fp16 in global.
__global__ void __launch_bounds__(256, 1)
gru_persistent(const float* __restrict__ gi, const float* __restrict__ w_hh,
               const float* __restrict__ b_hh,
               __half* __restrict__ hA, __half* __restrict__ hB)
{
    extern __shared__ __half smg[];
    __half* ws = smg;                          // [96][WS_LDH]
    __half* ht = smg + 96 * WS_LDH;            // 3 stages x [128][HT_LDH]
    constexpr int HTS = 128 * HT_LDH;

    const int tid  = threadIdx.x;
    const int lane = tid & 31, warp = tid >> 5;
    const int grp = lane >> 2, tig = lane & 3;
    const int sel = lane >> 3, rw = lane & 7;
    const int mt = blockIdx.x >> 4;
    const int jc = blockIdx.x & 15;
    const int m0 = mt * 128, j0 = jc * 32;

    // preload + convert resident w_hh slice to fp16
    for (int i4 = tid; i4 < 96 * 128; i4 += 256) {
        const int row = i4 >> 7, k4 = (i4 & 127) << 2;
        const int g = row >> 5, c = row & 31;
        float4 v = *(const float4*)(w_hh + (size_t)(g * kD + j0 + c) * kD + k4);
        *(__half2*)(ws + row * WS_LDH + k4)     = __floats2half2_rn(v.x, v.y);
        *(__half2*)(ws + row * WS_LDH + k4 + 2) = __floats2half2_rn(v.z, v.w);
    }

    float bhh0[12], bhh1[12];
#pragma unroll
    for (int ni = 0; ni < 12; ni++) {
        const int g = ni >> 2, j = j0 + (ni & 3) * 8 + tig * 2;
        bhh0[ni] = b_hh[g * kD + j];
        bhh1[ni] = b_hh[g * kD + j + 1];
    }
    __syncthreads();

    int lr[2], lk[2];   // h-tile: 128 rows x 4 16B-chunks (32 halves)
#pragma unroll
    for (int i = 0; i < 2; i++) { int l = tid + i * 256; lr[i] = l >> 2; lk[i] = (l & 3) << 3; }
    const uint32_t smb_ht = smem_u32(ht);
    const uint32_t smb_ws = smem_u32(ws);

    uint32_t adA, adB[6];
    {
        const int row = warp * 16 + ((sel & 1) << 3) + rw;
        adA = smb_ht + (uint32_t)(row * HT_LDH + ((sel >> 1) << 3)) * 2u;
    }
#pragma unroll
    for (int p = 0; p < 6; p++) {
        const int row = p * 16 + ((sel & 1) << 3) + rw;
        adB[p] = smb_ws + (uint32_t)(row * WS_LDH + ((sel >> 1) << 3)) * 2u;
    }

    for (int t = 0; t < kL; t++) {
        __half* src = (t & 1) ? hA : hB;
        __half* dst = (t & 1) ? hB : hA;

        float acc[12][4];
#pragma unroll
        for (int a = 0; a < 12; a++)
#pragma unroll
            for (int c = 0; c < 4; c++) acc[a][c] = 0.f;

        if (t > 0) {
            const __half* Ab = src + (size_t)m0 * kD;
            auto issue = [&](int kt) {        // kt in 0..15, BK=32 halves
                const int st = kt % 3;
                const int go = kt << 5;
#pragma unroll
                for (int i = 0; i < 2; i++) {
                    uint32_t sa = smb_ht + (uint32_t)(st * HTS + lr[i] * HT_LDH + lk[i]) * 2u;
                    cp16(sa, Ab + (size_t)lr[i] * kD + go + lk[i]);
                }
                asm volatile("cp.async.commit_group;\n");
            };
            issue(0); issue(1);

            for (int kt = 0; kt < 16; kt++) {
                if (kt + 1 < 16) asm volatile("cp.async.wait_group 1;\n");
                else             asm volatile("cp.async.wait_group 0;\n");
                __syncthreads();
                if (kt + 2 < 16) issue(kt + 2);

                const uint32_t stoff = (uint32_t)((kt % 3) * HTS) * 2u;
                const uint32_t kbyte = (uint32_t)(kt << 5) * 2u;
#pragma unroll
                for (int ks = 0; ks < 2; ks++) {   // two k16 steps
                    const uint32_t ko = (uint32_t)(ks * 16) * 2u;
                    uint32_t af[4], bq[6][4];
                    ldsm4(af, adA + stoff + ko);
#pragma unroll
                    for (int p = 0; p < 6; p++) ldsm4(bq[p], adB[p] + kbyte + ko);
#pragma unroll
                    for (int p = 0; p < 6; p++) {
                        mma_f16(acc[2 * p],     af, bq[p][0], bq[p][2]);
                        mma_f16(acc[2 * p + 1], af, bq[p][1], bq[p][3]);
                    }
                }
            }
            __syncthreads();
        }

        // fused gate update: acc[q]=gh_r, acc[q+4]=gh_z, acc[q+8]=gh_n
#pragma unroll
        for (int q = 0; q < 4; q++) {
#pragma unroll
            for (int s = 0; s < 2; s++) {
                const int b  = m0 + warp * 16 + grp + s * 8;
                const int jj = j0 + q * 8 + tig * 2;
                const float* gib = gi + ((size_t)b * kL + t) * (3 * kD);
                const float2 gr = *(const float2*)(gib + jj);
                const float2 gz = *(const float2*)(gib + kD + jj);
                const float2 gn = *(const float2*)(gib + 2 * kD + jj);
                float2 hp = make_float2(0.f, 0.f);
                if (t > 0) hp = __half22float2(*(const __half2*)(src + (size_t)b * kD + jj));
                const float r0 = sigm(gr.x + acc[q][2 * s]     + bhh0[q]);
                const float r1 = sigm(gr.y + acc[q][2 * s + 1] + bhh1[q]);
                const float z0 = sigm(gz.x + acc[q + 4][2 * s]     + bhh0[q + 4]);
                const float z1 = sigm(gz.y + acc[q + 4][2 * s + 1] + bhh1[q + 4]);
                const float n0 = tanhq(gn.x + r0 * (acc[q + 8][2 * s]     + bhh0[q + 8]));
                const float n1 = tanhq(gn.y + r1 * (acc[q + 8][2 * s + 1] + bhh1[q + 8]));
                const float h0 = (1.f - z0) * n0 + z0 * hp.x;
                const float h1 = (1.f - z1) * n1 + z1 * hp.y;
                *(__half2*)(dst + (size_t)b * kD + jj) = __floats2half2_rn(h0, h1);
            }
        }
        if (t < kL - 1) grid_barrier();
    }
}

// ---------------- host ----------------
extern "C" void kernel_launch(void* const* d_in, const int* in_sizes, int n_in,
                              void* d_out, int out_size)
{
    (void)in_sizes; (void)n_in; (void)out_size;
    const float* x     = (const float*)d_in[0];
    const float* w1    = (const float*)d_in[1];
    const float* b1    = (const float*)d_in[2];
    const float* w2    = (const float*)d_in[3];
    const float* b2    = (const float*)d_in[4];
    const float* w_ih  = (const float*)d_in[5];
    const float* w_hh  = (const float*)d_in[6];
    const float* b_ih  = (const float*)d_in[7];
    const float* b_hh  = (const float*)d_in[8];
    const float* lin_w = (const float*)d_in[9];
    const float* lin_b = (const float*)d_in[10];
    float* out = (float*)d_out;

    __half *h1, *h2, *hA, *hB, *rw2h, *rwihh, *rlinh;
    float *gi, *rw1;
    cudaGetSymbolAddress((void**)&h1,    g_h1);
    cudaGetSymbolAddress((void**)&h2,    g_h2);
    cudaGetSymbolAddress((void**)&gi,    g_gi);
    cudaGetSymbolAddress((void**)&hA,    g_hA);
    cudaGetSymbolAddress((void**)&hB,    g_hB);
    cudaGetSymbolAddress((void**)&rw1,   g_rw1);
    cudaGetSymbolAddress((void**)&rw2h,  g_rw2h);
    cudaGetSymbolAddress((void**)&rwihh, g_rwihh);
    cudaGetSymbolAddress((void**)&rlinh, g_rlinh);

    constexpr int T32_SMEM  = 4 * 2 * 128 * LDF * 4;                    // 81920
    constexpr int H16_SMEM  = 4 * 2 * 128 * LDH * 2;                    // 81920
    constexpr int GRU_SMEM  = (96 * WS_LDH + 3 * 128 * HT_LDH) * 2;     // 130560
    cudaFuncSetAttribute(gemm_t32,            cudaFuncAttributeMaxDynamicSharedMemorySize, T32_SMEM);
    cudaFuncSetAttribute(gemm_h<true,  true >, cudaFuncAttributeMaxDynamicSharedMemorySize, H16_SMEM);
    cudaFuncSetAttribute(gemm_h<false, false>, cudaFuncAttributeMaxDynamicSharedMemorySize, H16_SMEM);
    cudaFuncSetAttribute(gru_persistent,       cudaFuncAttributeMaxDynamicSharedMemorySize, GRU_SMEM);

    const int tm = kM / 128;   // 208

    // Launch order puts conv1 at kernel-launch #4 (the slot ncu captures).
    round_tf32<<<(kC1 * kA / 4 + 255) / 256, 256>>>(w1,    rw1,   kC1 * kA / 4);        // 1
    round_f16 <<<(kD * kC1 / 4 + 255) / 256, 256>>>(w2,    rw2h,  kD * kC1 / 4);        // 2
    round_f16 <<<(3 * kD * kD / 4 + 255) / 256, 256>>>(w_ih, rwihh, 3 * kD * kD / 4);   // 3

    // 4: conv1 [26624,8192] x [256,8192]^T (tf32; x cvt in-kernel; thresh; fp16 out)
    gemm_t32<<<tm * 2, 256, T32_SMEM>>>(x, rw1, b1, h1, kM, kC1, kA, tm * 2, 2);

    round_f16 <<<(kE * kD / 4 + 255) / 256, 256>>>(lin_w, rlinh, kE * kD / 4);          // 5

    // 6: conv2 [26624,256] x [512,256]^T (fp16; thresh; fp16 out)
    gemm_h<true, true ><<<tm * 4, 256, H16_SMEM>>>(h1, rw2h, b2, h2, kM, kD, kC1, tm * 4, 4);
    // 7: gi [26624,512] x [1536,512]^T (fp16; f32 out)
    gemm_h<false, false><<<tm * 12, 256, H16_SMEM>>>(h2, rwihh, b_ih, gi, kM, 3 * kD, kD, tm * 12, 12);

    // 8: fused persistent GRU (26 steps; kL even -> final h lands in hB)
    gru_persistent<<<128, 256, GRU_SMEM>>>(gi, w_hh, b_hh, hA, hB);

    // 9: out = h_last @ lin_w^T + lin_b (fp16 in, f32 out)
    gemm_h<false, false><<<8 * 8, 256, H16_SMEM>>>(hB, rlinh, lin_b, out, kB, kE, kD, 8 * 8, 8);
}

// round 11
// speedup vs baseline: 1.5756x; 1.1593x over previous
#include <cuda_runtime.h>
#include <cuda_fp16.h>
#include <cstdint>

namespace {
constexpr int kB  = 1024;
constexpr int kL  = 26;
constexpr int kA  = 8192;
constexpr int kC1 = 256;
constexpr int kD  = 512;
constexpr int kE  = 1024;
constexpr int kM  = kB * kL;      // 26624
constexpr float kThr = 1e-6f;
constexpr int LDH   = 40;         // fp16 gemm smem row stride (halves): BK=32 + 8
constexpr int WS_LDH = 520;       // GRU resident w_hh stride (halves)
constexpr int HT_LDH = 40;        // GRU h-tile stride (halves)
}

// ---------------- scratch (allocation-free) ----------------
__device__ __half g_xh[(size_t)kM * kA];        // 436 MB: x in fp16
__device__ __half g_h1[(size_t)kM * kC1];
__device__ __half g_h2[(size_t)kM * kD];
__device__ __half g_gi[(size_t)kM * 3 * kD];    // 82 MB: gi in fp16
__device__ __half g_hA[(size_t)kB * kD];
__device__ __half g_hB[(size_t)kB * kD];
__device__ __half g_rw1h[(size_t)kC1 * kA];
__device__ __half g_rw2h[(size_t)kD * kC1];
__device__ __half g_rwihh[(size_t)3 * kD * kD];
__device__ __half g_rlinh[(size_t)kE * kD];
__device__ unsigned g_bar_count = 0;
__device__ unsigned g_bar_gen   = 0;

// ---------------- helpers ----------------
__device__ __forceinline__ void mma_f16(float d[4], const uint32_t a[4], uint32_t b0, uint32_t b1) {
    asm volatile(
        "mma.sync.aligned.m16n8k16.row.col.f32.f16.f16.f32 "
        "{%0,%1,%2,%3}, {%4,%5,%6,%7}, {%8,%9}, {%0,%1,%2,%3};"
        : "+f"(d[0]), "+f"(d[1]), "+f"(d[2]), "+f"(d[3])
        : "r"(a[0]), "r"(a[1]), "r"(a[2]), "r"(a[3]), "r"(b0), "r"(b1));
}
__device__ __forceinline__ void cp16(uint32_t saddr, const void* g) {
    asm volatile("cp.async.cg.shared.global [%0], [%1], 16;\n" :: "r"(saddr), "l"(g));
}
__device__ __forceinline__ uint32_t smem_u32(const void* p) {
    uint32_t a;
    asm("{ .reg .u64 t; cvta.to.shared.u64 t, %1; cvt.u32.u64 %0, t; }" : "=r"(a) : "l"(p));
    return a;
}
__device__ __forceinline__ void ldsm4(uint32_t r[4], uint32_t saddr) {
    asm volatile("ldmatrix.sync.aligned.m8n8.x4.shared.b16 {%0,%1,%2,%3}, [%4];"
        : "=r"(r[0]), "=r"(r[1]), "=r"(r[2]), "=r"(r[3]) : "r"(saddr));
}
__device__ __forceinline__ uint32_t h2u(__half2 h) { return *reinterpret_cast<uint32_t*>(&h); }
__device__ __forceinline__ float sigm(float x)  { return 1.f / (1.f + __expf(-x)); }
__device__ __forceinline__ float tanhq(float x) { return 1.f - 2.f / (1.f + __expf(2.f * x)); }

// ---------------- conversions ----------------
__global__ void round_f16(const float* __restrict__ in, __half* __restrict__ out, int n4) {
    int i = blockIdx.x * blockDim.x + threadIdx.x;
    if (i < n4) {
        float4 v = ((const float4*)in)[i];
        *(__half2*)(out + (size_t)i * 4)     = __floats2half2_rn(v.x, v.y);
        *(__half2*)(out + (size_t)i * 4 + 2) = __floats2half2_rn(v.z, v.w);
    }
}
// x (fp32) -> fp16, 8 elements/thread/iter: 2x float4 read, 1x uint4 (8 halves) write
__global__ void cvt_x(const float* __restrict__ in, __half* __restrict__ out, int n8) {
    const int stride = gridDim.x * blockDim.x;
    for (int i = blockIdx.x * blockDim.x + threadIdx.x; i < n8; i += stride) {
        float4 a = ((const float4*)in)[(size_t)2 * i];
        float4 b = ((const float4*)in)[(size_t)2 * i + 1];
        uint4 o;
        o.x = h2u(__floats2half2_rn(a.x, a.y));
        o.y = h2u(__floats2half2_rn(a.z, a.w));
        o.z = h2u(__floats2half2_rn(b.x, b.y));
        o.w = h2u(__floats2half2_rn(b.z, b.w));
        ((uint4*)out)[i] = o;
    }
}

// ---------------- GEMM fp16 (all 4 feed-forward GEMMs) ----------------
// C[M,N] = A[M,K](f16) * B[N,K]^T(f16) + bias, f32 accum.  128x128 CTA,
// 256 thr, 4x2 warps (32x64 tiles), BK=32 halves, 4-stage cp.async ring,
// native ldmatrix b16, mma.m16n8k16, 1 sync/k-tile.
template<bool THRESH, bool OUT16>
__global__ void __launch_bounds__(256, 2)
gemm_h(const __half* __restrict__ Ag, const __half* __restrict__ Bg,
       const float* __restrict__ bias, void* __restrict__ Cgv,
       int M, int N, int K, int ntiles, int tn)
{
    extern __shared__ __half smh[];
    constexpr int AS = 128 * LDH;     // halves per A stage
    constexpr int SS = 2 * AS;
    const int tid  = threadIdx.x;
    const int lane = tid & 31, warp = tid >> 5;
    const int wr = warp >> 1, wc = warp & 1;
    const int grp = lane >> 2, tig = lane & 3;
    const int sel = lane >> 3, rw = lane & 7;
    const int NT = K >> 5;
    const uint32_t smb = smem_u32(smh);

    int lr[2], lk[2];   // 16B chunk = 8 halves; 128 rows x 4 chunks per operand
#pragma unroll
    for (int i = 0; i < 2; i++) { int l = tid + i * 256; lr[i] = l >> 2; lk[i] = (l & 3) << 3; }

    uint32_t adA[2], adB[4];
#pragma unroll
    for (int mi = 0; mi < 2; mi++) {
        const int row = wr * 32 + mi * 16 + ((sel & 1) << 3) + rw;
        adA[mi] = smb + (uint32_t)(row * LDH + ((sel >> 1) << 3)) * 2u;
    }
#pragma unroll
    for (int p = 0; p < 4; p++) {
        const int row = wc * 64 + p * 16 + ((sel & 1) << 3) + rw;
        adB[p] = smb + (uint32_t)(AS + row * LDH + ((sel >> 1) << 3)) * 2u;
    }

    for (int tile = blockIdx.x; tile < ntiles; tile += gridDim.x) {
        const int bm = (tile / tn) << 7;
        const int bn = (tile % tn) << 7;
        const __half* Ab = Ag + (size_t)bm * K;
        const __half* Bb = Bg + (size_t)bn * K;

        auto issue = [&](int kt) {
            const int st = kt & 3;
            const int go = kt << 5;
#pragma unroll
            for (int i = 0; i < 2; i++) {
                uint32_t sa = smb + (uint32_t)(st * SS + lr[i] * LDH + lk[i]) * 2u;
                cp16(sa,           Ab + (size_t)lr[i] * K + go + lk[i]);
                cp16(sa + AS * 2u, Bb + (size_t)lr[i] * K + go + lk[i]);
            }
            asm volatile("cp.async.commit_group;\n");
        };

        float acc[2][8][4];
#pragma unroll
        for (int a = 0; a < 2; a++)
#pragma unroll
            for (int b = 0; b < 8; b++)
#pragma unroll
                for (int c = 0; c < 4; c++) acc[a][b][c] = 0.f;

        issue(0); issue(1); issue(2);

        for (int kt = 0; kt < NT; kt++) {
            const int rem = NT - 1 - kt;
            if (rem >= 2)      asm volatile("cp.async.wait_group 2;\n");
            else if (rem == 1) asm volatile("cp.async.wait_group 1;\n");
            else               asm volatile("cp.async.wait_group 0;\n");
            __syncthreads();
            if (kt + 3 < NT) issue(kt + 3);

            const uint32_t stoff = (uint32_t)((kt & 3) * SS) * 2u;
#pragma unroll
            for (int ks = 0; ks < 2; ks++) {            // two k16 steps
                const uint32_t koff = stoff + (uint32_t)(ks * 16) * 2u;
                uint32_t af[2][4], bq[4][4];
#pragma unroll
                for (int mi = 0; mi < 2; mi++) ldsm4(af[mi], adA[mi] + koff);
#pragma unroll
                for (int p = 0; p < 4; p++) ldsm4(bq[p], adB[p] + koff);
#pragma unroll
                for (int mi = 0; mi < 2; mi++)
#pragma unroll
                    for (int p = 0; p < 4; p++) {
                        mma_f16(acc[mi][2 * p],     af[mi], bq[p][0], bq[p][2]);
                        mma_f16(acc[mi][2 * p + 1], af[mi], bq[p][1], bq[p][3]);
                    }
            }
        }
        __syncthreads();

#pragma unroll
        for (int mi = 0; mi < 2; mi++) {
            const int r0 = bm + wr * 32 + mi * 16 + grp;
#pragma unroll
            for (int ni = 0; ni < 8; ni++) {
                const int c0 = bn + wc * 64 + ni * 8 + tig * 2;
                const float b0 = bias[c0], b1 = bias[c0 + 1];
                float v00 = acc[mi][ni][0] + b0, v01 = acc[mi][ni][1] + b1;
                float v10 = acc[mi][ni][2] + b0, v11 = acc[mi][ni][3] + b1;
                if (THRESH) {
                    v00 = (v00 > kThr) ? v00 : 0.f;  v01 = (v01 > kThr) ? v01 : 0.f;
                    v10 = (v10 > kThr) ? v10 : 0.f;  v11 = (v11 > kThr) ? v11 : 0.f;
                }
                if (OUT16) {
                    __half* Cg = (__half*)Cgv;
                    *(__half2*)&Cg[(size_t)r0 * N + c0]       = __floats2half2_rn(v00, v01);
                    *(__half2*)&Cg[(size_t)(r0 + 8) * N + c0] = __floats2half2_rn(v10, v11);
                } else {
                    float* Cg = (float*)Cgv;
                    *(float2*)&Cg[(size_t)r0 * N + c0]       = make_float2(v00, v01);
                    *(float2*)&Cg[(size_t)(r0 + 8) * N + c0] = make_float2(v10, v11);
                }
            }
        }
    }
}

// ---------------- grid barrier (grid=128 <= 148 SMs, 1 CTA/SM) ----------------
__device__ __forceinline__ void grid_barrier() {
    __syncthreads();
    if (threadIdx.x == 0) {
        unsigned gen = *((volatile unsigned*)&g_bar_gen);
        __threadfence();
        if (atomicAdd(&g_bar_count, 1u) == gridDim.x - 1) {
            atomicExch(&g_bar_count, 0u);
            __threadfence();
            atomicAdd(&g_bar_gen, 1u);
        } else {
            while (*((volatile unsigned*)&g_bar_gen) == gen) { __nanosleep(32); }
            __threadfence();
        }
    }
    __syncthreads();
}

// ---------------- persistent fused GRU (fp16 operands + fp16 gi) --------------
__global__ void __launch_bounds__(256, 1)
gru_persistent(const __half* __restrict__ gi, const float* __restrict__ w_hh,
               const float* __restrict__ b_hh,
               __half* __restrict__ hA, __half* __restrict__ hB)
{
    extern __shared__ __half smg[];
    __half* ws = smg;                          // [96][WS_LDH]
    __half* ht = smg + 96 * WS_LDH;            // 3 stages x [128][HT_LDH]
    constexpr int HTS = 128 * HT_LDH;

    const int tid  = threadIdx.x;
    const int lane = tid & 31, warp = tid >> 5;
    const int grp = lane >> 2, tig = lane & 3;
    const int sel = lane >> 3, rw = lane & 7;
    const int mt = blockIdx.x >> 4;
    const int jc = blockIdx.x & 15;
    const int m0 = mt * 128, j0 = jc * 32;

    // preload + convert resident w_hh slice to fp16
    for (int i4 = tid; i4 < 96 * 128; i4 += 256) {
        const int row = i4 >> 7, k4 = (i4 & 127) << 2;
        const int g = row >> 5, c = row & 31;
        float4 v = *(const float4*)(w_hh + (size_t)(g * kD + j0 + c) * kD + k4);
        *(__half2*)(ws + row * WS_LDH + k4)     = __floats2half2_rn(v.x, v.y);
        *(__half2*)(ws + row * WS_LDH + k4 + 2) = __floats2half2_rn(v.z, v.w);
    }

    float bhh0[12], bhh1[12];
#pragma unroll
    for (int ni = 0; ni < 12; ni++) {
        const int g = ni >> 2, j = j0 + (ni & 3) * 8 + tig * 2;
        bhh0[ni] = b_hh[g * kD + j];
        bhh1[ni] = b_hh[g * kD + j + 1];
    }
    __syncthreads();

    int lr[2], lk[2];
#pragma unroll
    for (int i = 0; i < 2; i++) { int l = tid + i * 256; lr[i] = l >> 2; lk[i] = (l & 3) << 3; }
    const uint32_t smb_ht = smem_u32(ht);
    const uint32_t smb_ws = smem_u32(ws);

    uint32_t adA, adB[6];
    {
        const int row = warp * 16 + ((sel & 1) << 3) + rw;
        adA = smb_ht + (uint32_t)(row * HT_LDH + ((sel >> 1) << 3)) * 2u;
    }
#pragma unroll
    for (int p = 0; p < 6; p++) {
        const int row = p * 16 + ((sel & 1) << 3) + rw;
        adB[p] = smb_ws + (uint32_t)(row * WS_LDH + ((sel >> 1) << 3)) * 2u;
    }

    for (int t = 0; t < kL; t++) {
        __half* src = (t & 1) ? hA : hB;
        __half* dst = (t & 1) ? hB : hA;

        float acc[12][4];
#pragma unroll
        for (int a = 0; a < 12; a++)
#pragma unroll
            for (int c = 0; c < 4; c++) acc[a][c] = 0.f;

        if (t > 0) {
            const __half* Ab = src + (size_t)m0 * kD;
            auto issue = [&](int kt) {        // kt in 0..15, BK=32 halves
                const int st = kt % 3;
                const int go = kt << 5;
#pragma unroll
                for (int i = 0; i < 2; i++) {
                    uint32_t sa = smb_ht + (uint32_t)(st * HTS + lr[i] * HT_LDH + lk[i]) * 2u;
                    cp16(sa, Ab + (size_t)lr[i] * kD + go + lk[i]);
                }
                asm volatile("cp.async.commit_group;\n");
            };
            issue(0); issue(1);

            for (int kt = 0; kt < 16; kt++) {
                if (kt + 1 < 16) asm volatile("cp.async.wait_group 1;\n");
                else             asm volatile("cp.async.wait_group 0;\n");
                __syncthreads();
                if (kt + 2 < 16) issue(kt + 2);

                const uint32_t stoff = (uint32_t)((kt % 3) * HTS) * 2u;
                const uint32_t kbyte = (uint32_t)(kt << 5) * 2u;
#pragma unroll
                for (int ks = 0; ks < 2; ks++) {   // two k16 steps
                    const uint32_t ko = (uint32_t)(ks * 16) * 2u;
                    uint32_t af[4], bq[6][4];
                    ldsm4(af, adA + stoff + ko);
#pragma unroll
                    for (int p = 0; p < 6; p++) ldsm4(bq[p], adB[p] + kbyte + ko);
#pragma unroll
                    for (int p = 0; p < 6; p++) {
                        mma_f16(acc[2 * p],     af, bq[p][0], bq[p][2]);
                        mma_f16(acc[2 * p + 1], af, bq[p][1], bq[p][3]);
                    }
                }
            }
            __syncthreads();
        }

        // fused gate update: acc[q]=gh_r, acc[q+4]=gh_z, acc[q+8]=gh_n
#pragma unroll
        for (int q = 0; q < 4; q++) {
#pragma unroll
            for (int s = 0; s < 2; s++) {
                const int b  = m0 + warp * 16 + grp + s * 8;
                const int jj = j0 + q * 8 + tig * 2;
                const __half* gib = gi + ((size_t)b * kL + t) * (3 * kD);
                const float2 gr = __half22float2(*(const __half2*)(gib + jj));
                const float2 gz = __half22float2(*(const __half2*)(gib + kD + jj));
                const float2 gn = __half22float2(*(const __half2*)(gib + 2 * kD + jj));
                float2 hp = make_float2(0.f, 0.f);
                if (t > 0) hp = __half22float2(*(const __half2*)(src + (size_t)b * kD + jj));
                const float r0 = sigm(gr.x + acc[q][2 * s]     + bhh0[q]);
                const float r1 = sigm(gr.y + acc[q][2 * s + 1] + bhh1[q]);
                const float z0 = sigm(gz.x + acc[q + 4][2 * s]     + bhh0[q + 4]);
                const float z1 = sigm(gz.y + acc[q + 4][2 * s + 1] + bhh1[q + 4]);
                const float n0 = tanhq(gn.x + r0 * (acc[q + 8][2 * s]     + bhh0[q + 8]));
                const float n1 = tanhq(gn.y + r1 * (acc[q + 8][2 * s + 1] + bhh1[q + 8]));
                const float h0 = (1.f - z0) * n0 + z0 * hp.x;
                const float h1 = (1.f - z1) * n1 + z1 * hp.y;
                *(__half2*)(dst + (size_t)b * kD + jj) = __floats2half2_rn(h0, h1);
            }
        }
        if (t < kL - 1) grid_barrier();
    }
}

// ---------------- host ----------------
extern "C" void kernel_launch(void* const* d_in, const int* in_sizes, int n_in,
                              void* d_out, int out_size)
{
    (void)in_sizes; (void)n_in; (void)out_size;
    const float* x     = (const float*)d_in[0];
    const float* w1    = (const float*)d_in[1];
    const float* b1    = (const float*)d_in[2];
    const float* w2    = (const float*)d_in[3];
    const float* b2    = (const float*)d_in[4];
    const float* w_ih  = (const float*)d_in[5];
    const float* w_hh  = (const float*)d_in[6];
    const float* b_ih  = (const float*)d_in[7];
    const float* b_hh  = (const float*)d_in[8];
    const float* lin_w = (const float*)d_in[9];
    const float* lin_b = (const float*)d_in[10];
    float* out = (float*)d_out;

    __half *xh, *h1, *h2, *gi, *hA, *hB, *rw1h, *rw2h, *rwihh, *rlinh;
    cudaGetSymbolAddress((void**)&xh,    g_xh);
    cudaGetSymbolAddress((void**)&h1,    g_h1);
    cudaGetSymbolAddress((void**)&h2,    g_h2);
    cudaGetSymbolAddress((void**)&gi,    g_gi);
    cudaGetSymbolAddress((void**)&hA,    g_hA);
    cudaGetSymbolAddress((void**)&hB,    g_hB);
    cudaGetSymbolAddress((void**)&rw1h,  g_rw1h);
    cudaGetSymbolAddress((void**)&rw2h,  g_rw2h);
    cudaGetSymbolAddress((void**)&rwihh, g_rwihh);
    cudaGetSymbolAddress((void**)&rlinh, g_rlinh);

    constexpr int H16_SMEM  = 4 * 2 * 128 * LDH * 2;                    // 81920
    constexpr int GRU_SMEM  = (96 * WS_LDH + 3 * 128 * HT_LDH) * 2;     // 130560
    cudaFuncSetAttribute(gemm_h<true,  true >, cudaFuncAttributeMaxDynamicSharedMemorySize, H16_SMEM);
    cudaFuncSetAttribute(gemm_h<false, true >, cudaFuncAttributeMaxDynamicSharedMemorySize, H16_SMEM);
    cudaFuncSetAttribute(gemm_h<false, false>, cudaFuncAttributeMaxDynamicSharedMemorySize, H16_SMEM);
    cudaFuncSetAttribute(gru_persistent,       cudaFuncAttributeMaxDynamicSharedMemorySize, GRU_SMEM);

    const int tm = kM / 128;   // 208

    // 1: x -> fp16 (27.3M iters of 32B read + 16B write, grid-stride)
    cvt_x<<<4096, 256>>>(x, xh, kM * kA / 8);
    // 2-3: weight converts (order keeps conv1 at ncu's captured slot #4)
    round_f16<<<(kC1 * kA / 4 + 255) / 256, 256>>>(w1, rw1h, kC1 * kA / 4);
    round_f16<<<(kD * kC1 / 4 + 255) / 256, 256>>>(w2, rw2h, kD * kC1 / 4);

    // 4: conv1 [26624,8192] x [256,8192]^T (fp16, thresh, fp16 out)
    gemm_h<true, true ><<<tm * 2, 256, H16_SMEM>>>(xh, rw1h, b1, h1, kM, kC1, kA, tm * 2, 2);

    // 5: w_ih convert
    round_f16<<<(3 * kD * kD / 4 + 255) / 256, 256>>>(w_ih, rwihh, 3 * kD * kD / 4);
    // 6: conv2 [26624,256] x [512,256]^T (fp16, thresh, fp16 out)
    gemm_h<true, true ><<<tm * 4, 256, H16_SMEM>>>(h1, rw2h, b2, h2, kM, kD, kC1, tm * 4, 4);
    // 7: gi [26624,512] x [1536,512]^T (fp16 in/out)
    gemm_h<false, true ><<<tm * 12, 256, H16_SMEM>>>(h2, rwihh, b_ih, gi, kM, 3 * kD, kD, tm * 12, 12);
    // 8: lin_w convert
    round_f16<<<(kE * kD / 4 + 255) / 256, 256>>>(lin_w, rlinh, kE * kD / 4);
    // 9: fused persistent GRU (26 steps; kL even -> final h lands in hB)
    gru_persistent<<<128, 256, GRU_SMEM>>>(gi, w_hh, b_hh, hA, hB);
    // 10: out = h_last @ lin_w^T + lin_b (fp16 in, f32 out)
    gemm_h<false, false><<<8 * 8, 256, H16_SMEM>>>(hB, rlinh, lin_b, out, kB, kE, kD, 8 * 8, 8);
}